// round 14
// baseline (speedup 1.0000x reference)
#include <cuda_runtime.h>
#include <cuda_fp16.h>
#include <cstdint>
#include <math.h>

#define M_DIM 16384
#define K_DIM 768
#define N_DIM 3072

// ---------------- scratch (no cudaMalloc allowed) ----------------
__device__ uint16_t g_A[M_DIM * K_DIM];    // fp16 bits, LN output
__device__ uint16_t g_B[N_DIM * K_DIM];    // fp16 bits, W transposed [N, K]
__device__ int g_cnt_a[M_DIM / 128];       // LN producer counters (zero-init)

// ---------------- helpers ----------------
__device__ __forceinline__ uint32_t smem_u32(const void* p) {
    uint32_t a;
    asm("{ .reg .u64 t; cvta.to.shared.u64 t, %1; cvt.u32.u64 %0, t; }" : "=r"(a) : "l"(p));
    return a;
}
__device__ __forceinline__ uint32_t pack_h2(float lo, float hi) {
    uint32_t r;
    asm("cvt.rn.f16x2.f32 %0, %1, %2;" : "=r"(r) : "f"(hi), "f"(lo));
    return r;
}
__device__ __forceinline__ void cp_async16(uint32_t dst, const void* src) {
    asm volatile("cp.async.cg.shared.global [%0], [%1], 16;"
                 :: "r"(dst), "l"(__cvta_generic_to_global(src)) : "memory");
}
#define CP_COMMIT() asm volatile("cp.async.commit_group;" ::: "memory")
#define CP_WAIT(n)  asm volatile("cp.async.wait_group %0;" :: "n"(n) : "memory")

__device__ __forceinline__ void ldmatrix_x4(uint32_t* r, uint32_t addr) {
    asm volatile("ldmatrix.sync.aligned.m8n8.x4.shared.b16 {%0,%1,%2,%3}, [%4];"
                 : "=r"(r[0]), "=r"(r[1]), "=r"(r[2]), "=r"(r[3]) : "r"(addr));
}
__device__ __forceinline__ void mma_f16(float* d, const uint32_t* a,
                                        uint32_t b0, uint32_t b1) {
    asm volatile(
        "mma.sync.aligned.m16n8k16.row.col.f32.f16.f16.f32 "
        "{%0,%1,%2,%3}, {%4,%5,%6,%7}, {%8,%9}, {%0,%1,%2,%3};"
        : "+f"(d[0]), "+f"(d[1]), "+f"(d[2]), "+f"(d[3])
        : "r"(a[0]), "r"(a[1]), "r"(a[2]), "r"(a[3]), "r"(b0), "r"(b1));
}
__device__ __forceinline__ float gelu_exact(float h) {
    return 0.5f * h * (1.0f + erff(h * 0.70710678118654752f));
}

// ---------------------------------------------------------------------------
// Kernel 1: transpose W [K,N] -> [N,K] fp16 (unchanged)
// ---------------------------------------------------------------------------
__global__ __launch_bounds__(256) void wt_h_kernel(const float* __restrict__ W)
{
    __shared__ float tile[64][33];
    const int tx = threadIdx.x, ty = threadIdx.y;
    const int n0 = blockIdx.x * 32, k0 = blockIdx.y * 64;

    #pragma unroll
    for (int j = 0; j < 8; j++)
        tile[ty + 8 * j][tx] = W[(size_t)(k0 + ty + 8 * j) * N_DIM + n0 + tx];
    __syncthreads();

    uint4 o;
    o.x = pack_h2(tile[ty * 8 + 0][tx], tile[ty * 8 + 1][tx]);
    o.y = pack_h2(tile[ty * 8 + 2][tx], tile[ty * 8 + 3][tx]);
    o.z = pack_h2(tile[ty * 8 + 4][tx], tile[ty * 8 + 5][tx]);
    o.w = pack_h2(tile[ty * 8 + 6][tx], tile[ty * 8 + 7][tx]);
    *(uint4*)&g_B[(size_t)(n0 + tx) * K_DIM + k0 + ty * 8] = o;
}

// ---------------------------------------------------------------------------
// Kernel 2: FUSED LN + GEMM.
// CTA 128x128, warp 32x64, BK=64, 2-stage cp.async (dyn smem 73.7KB),
// 12 steps, phase-of-2 unroll (all smem offsets immediates).
// ---------------------------------------------------------------------------
#define BM 128
#define BN 128
#define BK 64
#define ROWH 72                        // halves per row (64 data + 8 pad) = 144B
#define NSTEP 12                       // 768 / 64
#define STG (BM * ROWH * 2)            // 18432 B per operand per stage
#define ROWS64 (64 * ROWH * 2)         // +64 rows = 9216 B
#define MT16 (16 * ROWH * 2)           // +16 rows = 2304 B
#define SMEM_BYTES (2 * 2 * STG)       // 73728 B
#define NBX (N_DIM / BN)               // 24

__global__ __launch_bounds__(256, 2) void gemm_fused_kernel(
    const float* __restrict__ x,
    const float* __restrict__ gamma,
    const float* __restrict__ beta,
    const float* __restrict__ bias,
    float* __restrict__ C)
{
    extern __shared__ uint16_t sdyn[];
    __shared__ float lred[4][2][2];

    const int tid = threadIdx.x;
    const int bid = blockIdx.x;
    const int bx = bid % NBX;
    const int by = bid / NBX;
    const int bn = bx * BN;
    const int bm = by * BM;

    // ---------------- LN producer phase (bx < 8) ----------------
    if (bx < 8) {
        const int t = tid & 63;
        const int rl = tid >> 6;
        const int wir = t >> 5;
        #pragma unroll 1
        for (int p = 0; p < 4; p++) {
            const int row = bm + bx * 16 + p * 4 + rl;
            const float4* xr = (const float4*)(x + (size_t)row * K_DIM);
            float4 v[3];
            #pragma unroll
            for (int j = 0; j < 3; j++) v[j] = xr[t + 64 * j];

            float s = 0.0f, s2 = 0.0f;
            #pragma unroll
            for (int j = 0; j < 3; j++) {
                s  += v[j].x + v[j].y + v[j].z + v[j].w;
                s2 += v[j].x * v[j].x + v[j].y * v[j].y
                    + v[j].z * v[j].z + v[j].w * v[j].w;
            }
            #pragma unroll
            for (int off = 16; off > 0; off >>= 1) {
                s  += __shfl_xor_sync(0xffffffffu, s,  off);
                s2 += __shfl_xor_sync(0xffffffffu, s2, off);
            }
            __syncthreads();
            if ((t & 31) == 0) { lred[rl][wir][0] = s; lred[rl][wir][1] = s2; }
            __syncthreads();
            s  = lred[rl][0][0] + lred[rl][1][0];
            s2 = lred[rl][0][1] + lred[rl][1][1];

            const float inv_n = 1.0f / (float)K_DIM;
            const float mu  = s * inv_n;
            const float var = fmaxf(s2 * inv_n - mu * mu, 0.0f);
            const float rstd = rsqrtf(var + 1e-12f);

            uint2* outr = (uint2*)(g_A + (size_t)row * K_DIM);
            #pragma unroll
            for (int j = 0; j < 3; j++) {
                const float4 g = ((const float4*)gamma)[t + 64 * j];
                const float4 be = ((const float4*)beta)[t + 64 * j];
                uint2 o;
                o.x = pack_h2((v[j].x - mu) * rstd * g.x + be.x,
                              (v[j].y - mu) * rstd * g.y + be.y);
                o.y = pack_h2((v[j].z - mu) * rstd * g.z + be.z,
                              (v[j].w - mu) * rstd * g.w + be.w);
                outr[t + 64 * j] = o;
            }
        }
        __threadfence();
        __syncthreads();
        if (tid == 0) atomicAdd(&g_cnt_a[by], 1);
    }

    // ---------------- wait for this M-block's LN ----------------
    if (tid == 0) {
        while (*(volatile int*)&g_cnt_a[by] < 8) { }
        __threadfence();
    }
    __syncthreads();

    // ---------------- GEMM ----------------
    const int wid = tid >> 5, lane = tid & 31;
    const int wm = (wid >> 1) * 32;   // 4 warps along M
    const int wn = (wid & 1) * 64;    // 2 warps along N

    float acc[2][8][4];
    #pragma unroll
    for (int mt = 0; mt < 2; mt++)
        #pragma unroll
        for (int nt = 0; nt < 8; nt++)
            #pragma unroll
            for (int q = 0; q < 4; q++) acc[mt][nt][q] = 0.0f;

    const uint32_t sA0 = smem_u32(sdyn);                 // stages 0,1 of A
    const uint32_t sB0 = sA0 + 2 * STG;                  // stages 0,1 of B

    // cp.async geometry: per stage per operand 1024 x 16B chunks; 4/thread:
    // rows (tid>>2) and (tid>>2)+64, chunk pair (tid&3)*2 .. +1.
    const int r_ld = tid >> 2;             // 0..63
    const int c_ld = (tid & 3) * 16;       // half offset (two 16B chunks)

    uint32_t awA[2], awB[2];               // write bases (row r_ld, chunk pair)
    uint32_t raA[2], raB[2];               // ldmatrix bases (mt=0, kk=0)
    #pragma unroll
    for (int s = 0; s < 2; s++) {
        const uint32_t wo = (uint32_t)(r_ld * ROWH + c_ld) * 2;
        awA[s] = sA0 + s * STG + wo;
        awB[s] = sB0 + s * STG + wo;
        raA[s] = sA0 + s * STG
               + (uint32_t)((wm + (lane & 15)) * ROWH) * 2 + (lane >> 4) * 16;
        raB[s] = sB0 + s * STG
               + (uint32_t)((wn + (lane & 15)) * ROWH) * 2 + (lane >> 4) * 16;
    }

    const uint16_t* pA = g_A + (size_t)(bm + r_ld) * K_DIM + c_ld;
    const uint16_t* pB = g_B + (size_t)(bn + r_ld) * K_DIM + c_ld;
    const size_t rowskip = (size_t)64 * K_DIM;

    // ---- prologue: step 0 into stage 0 ----
    #pragma unroll
    for (int i = 0; i < 2; i++) {          // two row groups
        const size_t go = (size_t)i * rowskip;
        const uint32_t so = i * ROWS64;
        cp_async16(awA[0] + so,      pA + go);
        cp_async16(awA[0] + so + 16, pA + go + 8);
        cp_async16(awB[0] + so,      pB + go);
        cp_async16(awB[0] + so + 16, pB + go + 8);
    }
    CP_COMMIT();
    pA += BK;
    pB += BK;

    // ---- mainloop: 6 iterations x 2 compile-time phases ----
    for (int it = 0; it < NSTEP; it += 2) {
        #pragma unroll
        for (int ph = 0; ph < 2; ph++) {
            const int step = it + ph;      // stage == ph
            CP_WAIT(0);
            __syncthreads();

            // prefetch step+1 into other stage (its readers finished step-1)
            if (step + 1 < NSTEP) {
                const int ps = ph ^ 1;
                #pragma unroll
                for (int i = 0; i < 2; i++) {
                    const size_t go = (size_t)i * rowskip;
                    const uint32_t so = i * ROWS64;
                    cp_async16(awA[ps] + so,      pA + go);
                    cp_async16(awA[ps] + so + 16, pA + go + 8);
                    cp_async16(awB[ps] + so,      pB + go);
                    cp_async16(awB[ps] + so + 16, pB + go + 8);
                }
                CP_COMMIT();
                pA += BK;
                pB += BK;
            }

            #pragma unroll
            for (int kk = 0; kk < 4; kk++) {
                uint32_t a[2][4];
                #pragma unroll
                for (int mt = 0; mt < 2; mt++)
                    ldmatrix_x4(a[mt], raA[ph] + mt * MT16 + kk * 32);
                uint32_t b[4][4];
                #pragma unroll
                for (int g = 0; g < 4; g++)
                    ldmatrix_x4(b[g], raB[ph] + g * MT16 + kk * 32);
                #pragma unroll
                for (int mt = 0; mt < 2; mt++)
                    #pragma unroll
                    for (int nt = 0; nt < 8; nt++)
                        mma_f16(acc[mt][nt], a[mt],
                                b[nt >> 1][nt & 1], b[nt >> 1][2 + (nt & 1)]);
            }
        }
    }

    // ---- epilogue: bias + exact erf GELU ----
    const int r0 = bm + wm + (lane >> 2);
    const int c0 = bn + wn + (lane & 3) * 2;
    #pragma unroll
    for (int mt = 0; mt < 2; mt++) {
        #pragma unroll
        for (int nt = 0; nt < 8; nt++) {
            const int col = c0 + nt * 8;
            const float b0 = __ldg(&bias[col]), b1 = __ldg(&bias[col + 1]);
            #pragma unroll
            for (int half = 0; half < 2; half++) {
                const int row = r0 + mt * 16 + half * 8;
                float2 o;
                o.x = gelu_exact(acc[mt][nt][half * 2 + 0] + b0);
                o.y = gelu_exact(acc[mt][nt][half * 2 + 1] + b1);
                *(float2*)&C[(size_t)row * N_DIM + col] = o;
            }
        }
    }
}

// ---------------------------------------------------------------------------
extern "C" void kernel_launch(void* const* d_in, const int* in_sizes, int n_in,
                              void* d_out, int out_size)
{
    const float* x     = (const float*)d_in[0];
    const float* gamma = (const float*)d_in[1];
    const float* beta  = (const float*)d_in[2];
    const float* W     = (const float*)d_in[3];
    const float* b     = (const float*)d_in[4];
    float* out = (float*)d_out;

    cudaFuncSetAttribute(gemm_fused_kernel,
                         cudaFuncAttributeMaxDynamicSharedMemorySize, SMEM_BYTES);

    wt_h_kernel<<<dim3(N_DIM / 32, K_DIM / 64), dim3(32, 8)>>>(W);
    gemm_fused_kernel<<<NBX * (M_DIM / BM), 256, SMEM_BYTES>>>(
        x, gamma, beta, b, out);
}

// round 15
// speedup vs baseline: 1.0034x; 1.0034x over previous
#include <cuda_runtime.h>
#include <cuda_fp16.h>
#include <cstdint>
#include <math.h>

#define M_DIM 16384
#define K_DIM 768
#define N_DIM 3072

// ---------------- scratch (no cudaMalloc allowed) ----------------
__device__ uint16_t g_A[M_DIM * K_DIM];    // fp16 bits, LN output
__device__ uint16_t g_B[N_DIM * K_DIM];    // fp16 bits, W transposed [N, K]

// ---------------- helpers ----------------
__device__ __forceinline__ uint32_t smem_u32(const void* p) {
    uint32_t a;
    asm("{ .reg .u64 t; cvta.to.shared.u64 t, %1; cvt.u32.u64 %0, t; }" : "=r"(a) : "l"(p));
    return a;
}
__device__ __forceinline__ uint32_t pack_h2(float lo, float hi) {
    uint32_t r;
    asm("cvt.rn.f16x2.f32 %0, %1, %2;" : "=r"(r) : "f"(hi), "f"(lo));
    return r;
}
__device__ __forceinline__ void cp_async16(uint32_t dst, const void* src) {
    asm volatile("cp.async.cg.shared.global [%0], [%1], 16;"
                 :: "r"(dst), "l"(__cvta_generic_to_global(src)) : "memory");
}
#define CP_COMMIT() asm volatile("cp.async.commit_group;" ::: "memory")
#define CP_WAIT(n)  asm volatile("cp.async.wait_group %0;" :: "n"(n) : "memory")

__device__ __forceinline__ void ldmatrix_x4(uint32_t* r, uint32_t addr) {
    asm volatile("ldmatrix.sync.aligned.m8n8.x4.shared.b16 {%0,%1,%2,%3}, [%4];"
                 : "=r"(r[0]), "=r"(r[1]), "=r"(r[2]), "=r"(r[3]) : "r"(addr));
}
__device__ __forceinline__ void mma_f16(float* d, const uint32_t* a,
                                        uint32_t b0, uint32_t b1) {
    asm volatile(
        "mma.sync.aligned.m16n8k16.row.col.f32.f16.f16.f32 "
        "{%0,%1,%2,%3}, {%4,%5,%6,%7}, {%8,%9}, {%0,%1,%2,%3};"
        : "+f"(d[0]), "+f"(d[1]), "+f"(d[2]), "+f"(d[3])
        : "r"(a[0]), "r"(a[1]), "r"(a[2]), "r"(a[3]), "r"(b0), "r"(b1));
}
__device__ __forceinline__ float gelu_exact(float h) {
    return 0.5f * h * (1.0f + erff(h * 0.70710678118654752f));
}

// ---------------------------------------------------------------------------
// Kernel 1: LayerNorm -> fp16 (R13 version, unchanged)
// ---------------------------------------------------------------------------
__global__ __launch_bounds__(256) void ln_h_kernel(
    const float* __restrict__ x,
    const float* __restrict__ gamma,
    const float* __restrict__ beta)
{
    const int tid = threadIdx.x;
    const int rloc = tid >> 6;
    const int t = tid & 63;
    const int row = blockIdx.x * 4 + rloc;
    const float4* xr = (const float4*)(x + (size_t)row * K_DIM);

    float4 v[3];
    #pragma unroll
    for (int j = 0; j < 3; j++) v[j] = xr[t + 64 * j];

    float s = 0.0f, s2 = 0.0f;
    #pragma unroll
    for (int j = 0; j < 3; j++) {
        s  += v[j].x + v[j].y + v[j].z + v[j].w;
        s2 += v[j].x * v[j].x + v[j].y * v[j].y + v[j].z * v[j].z + v[j].w * v[j].w;
    }
    #pragma unroll
    for (int off = 16; off > 0; off >>= 1) {
        s  += __shfl_xor_sync(0xffffffffu, s,  off);
        s2 += __shfl_xor_sync(0xffffffffu, s2, off);
    }
    __shared__ float red[4][2][2];
    const int wir = (t >> 5);
    if ((t & 31) == 0) { red[rloc][wir][0] = s; red[rloc][wir][1] = s2; }
    __syncthreads();
    s  = red[rloc][0][0] + red[rloc][1][0];
    s2 = red[rloc][0][1] + red[rloc][1][1];

    const float inv_n = 1.0f / (float)K_DIM;
    const float mu  = s * inv_n;
    const float var = fmaxf(s2 * inv_n - mu * mu, 0.0f);
    const float rstd = rsqrtf(var + 1e-12f);

    uint2* outr = (uint2*)(g_A + (size_t)row * K_DIM);
    #pragma unroll
    for (int j = 0; j < 3; j++) {
        const float4 g = ((const float4*)gamma)[t + 64 * j];
        const float4 be = ((const float4*)beta)[t + 64 * j];
        uint2 o;
        o.x = pack_h2((v[j].x - mu) * rstd * g.x + be.x,
                      (v[j].y - mu) * rstd * g.y + be.y);
        o.y = pack_h2((v[j].z - mu) * rstd * g.z + be.z,
                      (v[j].w - mu) * rstd * g.w + be.w);
        outr[t + 64 * j] = o;
    }
}

// ---------------------------------------------------------------------------
// Kernel 2: transpose W [K,N] -> [N,K] fp16 (unchanged)
// ---------------------------------------------------------------------------
__global__ __launch_bounds__(256) void wt_h_kernel(const float* __restrict__ W)
{
    __shared__ float tile[64][33];
    const int tx = threadIdx.x, ty = threadIdx.y;
    const int n0 = blockIdx.x * 32, k0 = blockIdx.y * 64;

    #pragma unroll
    for (int j = 0; j < 8; j++)
        tile[ty + 8 * j][tx] = W[(size_t)(k0 + ty + 8 * j) * N_DIM + n0 + tx];
    __syncthreads();

    uint4 o;
    o.x = pack_h2(tile[ty * 8 + 0][tx], tile[ty * 8 + 1][tx]);
    o.y = pack_h2(tile[ty * 8 + 2][tx], tile[ty * 8 + 3][tx]);
    o.z = pack_h2(tile[ty * 8 + 4][tx], tile[ty * 8 + 5][tx]);
    o.w = pack_h2(tile[ty * 8 + 6][tx], tile[ty * 8 + 7][tx]);
    *(uint4*)&g_B[(size_t)(n0 + tx) * K_DIM + k0 + ty * 8] = o;
}

// ---------------------------------------------------------------------------
// Kernel 3: fp16 GEMM (R13 base: CTA 128x128, warp 32x64, BK=32, 3-stage,
// phase-of-3 unroll). NEW: intra-step fragment double-buffering — B fragment
// for group g+1 loads while group g's MMAs run; kk=1's A fragments preload
// during kk=0. Fragment liveness unchanged (24 regs).
// ---------------------------------------------------------------------------
#define BM 128
#define BN 128
#define BK 32
#define ROWH 40
#define NSTEP 24
#define NSTAGE 3
#define STG_A (BM * ROWH * 2)     // 10240 B
#define STG_B (BN * ROWH * 2)     // 10240 B
#define CHUNK2 (64 * ROWH * 2)    // +64 rows = 5120 B
#define MT16 (16 * ROWH * 2)      // +16 rows = 1280 B

__global__ __launch_bounds__(256, 2) void gemm_f16_kernel(
    const float* __restrict__ bias, float* __restrict__ C)
{
    __shared__ uint16_t As[NSTAGE][BM * ROWH];
    __shared__ uint16_t Bs[NSTAGE][BN * ROWH];

    const int tid = threadIdx.x;
    const int wid = tid >> 5, lane = tid & 31;
    const int bn = blockIdx.x * BN;
    const int bm = blockIdx.y * BM;
    const int wm = (wid >> 1) * 32;   // 4 warps along M
    const int wn = (wid & 1) * 64;    // 2 warps along N

    float acc[2][8][4];
    #pragma unroll
    for (int mt = 0; mt < 2; mt++)
        #pragma unroll
        for (int nt = 0; nt < 8; nt++)
            #pragma unroll
            for (int q = 0; q < 4; q++) acc[mt][nt][q] = 0.0f;

    const uint32_t sA0 = smem_u32(&As[0][0]);
    const uint32_t sB0 = smem_u32(&Bs[0][0]);

    // ---- loop-invariant addresses ----
    const int r_ld = tid >> 2;             // 0..63
    const int c_ld = (tid & 3) * 8;

    uint32_t awA[NSTAGE], awB[NSTAGE];     // cp.async write bases (chunk 0)
    uint32_t raA[NSTAGE], raB[NSTAGE];     // ldmatrix read bases (mt=0, kk=0)
    #pragma unroll
    for (int s = 0; s < NSTAGE; s++) {
        awA[s] = sA0 + s * STG_A + (uint32_t)(r_ld * ROWH + c_ld) * 2;
        awB[s] = sB0 + s * STG_B + (uint32_t)(r_ld * ROWH + c_ld) * 2;
        raA[s] = sA0 + s * STG_A
               + (uint32_t)((wm + (lane & 15)) * ROWH) * 2 + (lane >> 4) * 16;
        raB[s] = sB0 + s * STG_B
               + (uint32_t)((wn + (lane & 15)) * ROWH) * 2 + (lane >> 4) * 16;
    }

    const uint16_t* pA = g_A + (size_t)(bm + r_ld) * K_DIM + c_ld;
    const uint16_t* pB = g_B + (size_t)(bn + r_ld) * K_DIM + c_ld;
    const size_t rowskip = (size_t)64 * K_DIM;

    // ---- prologue: steps 0,1 into stages 0,1 ----
    #pragma unroll
    for (int s = 0; s < 2; s++) {
        cp_async16(awA[s],          pA + s * BK);
        cp_async16(awA[s] + CHUNK2, pA + s * BK + rowskip);
        cp_async16(awB[s],          pB + s * BK);
        cp_async16(awB[s] + CHUNK2, pB + s * BK + rowskip);
        CP_COMMIT();
    }
    pA += 2 * BK;
    pB += 2 * BK;

    // ---- mainloop: 8 iterations x 3 compile-time phases ----
    for (int it = 0; it < NSTEP; it += 3) {
        #pragma unroll
        for (int ph = 0; ph < 3; ph++) {
            const int step = it + ph;          // stage == ph
            if (step < NSTEP - 1) { CP_WAIT(1); } else { CP_WAIT(0); }
            __syncthreads();

            // preload first fragments of this step (kk=0: both A, B group 0)
            uint32_t afr[2][2][4];             // [kk][mt][4]
            uint32_t bfr[2][4];                // double buffer
            #pragma unroll
            for (int mt = 0; mt < 2; mt++)
                ldmatrix_x4(afr[0][mt], raA[ph] + mt * MT16);
            ldmatrix_x4(bfr[0], raB[ph]);

            // prefetch step+2 into stage (ph+2)%3 (read last at step-1);
            // issues while the LDSMs above are in flight
            if (step + 2 < NSTEP) {
                const int ps = (ph + 2) % 3;
                cp_async16(awA[ps],          pA);
                cp_async16(awA[ps] + CHUNK2, pA + rowskip);
                cp_async16(awB[ps],          pB);
                cp_async16(awB[ps] + CHUNK2, pB + rowskip);
                CP_COMMIT();
                pA += BK;
                pB += BK;
            }

            #pragma unroll
            for (int kk = 0; kk < 2; kk++) {
                if (kk == 0) {
                    // preload kk=1 A fragments under kk=0 compute
                    #pragma unroll
                    for (int mt = 0; mt < 2; mt++)
                        ldmatrix_x4(afr[1][mt], raA[ph] + mt * MT16 + 32);
                }
                #pragma unroll
                for (int g = 0; g < 4; g++) {
                    const int c = kk * 4 + g;
                    if (c + 1 < 8) {
                        // load next B fragment before this group's MMAs
                        const int nkk = (c + 1) >> 2, ng = (c + 1) & 3;
                        ldmatrix_x4(bfr[(c + 1) & 1],
                                    raB[ph] + ng * MT16 + nkk * 32);
                    }
                    const uint32_t* bc = bfr[c & 1];
                    #pragma unroll
                    for (int mt = 0; mt < 2; mt++) {
                        mma_f16(acc[mt][2 * g + 0], afr[kk][mt], bc[0], bc[2]);
                        mma_f16(acc[mt][2 * g + 1], afr[kk][mt], bc[1], bc[3]);
                    }
                }
            }
        }
    }

    // ---- epilogue: bias + exact erf GELU ----
    const int r0 = bm + wm + (lane >> 2);
    const int c0 = bn + wn + (lane & 3) * 2;
    #pragma unroll
    for (int mt = 0; mt < 2; mt++) {
        #pragma unroll
        for (int nt = 0; nt < 8; nt++) {
            const int col = c0 + nt * 8;
            const float b0 = __ldg(&bias[col]), b1 = __ldg(&bias[col + 1]);
            #pragma unroll
            for (int half = 0; half < 2; half++) {
                const int row = r0 + mt * 16 + half * 8;
                float2 o;
                o.x = gelu_exact(acc[mt][nt][half * 2 + 0] + b0);
                o.y = gelu_exact(acc[mt][nt][half * 2 + 1] + b1);
                *(float2*)&C[(size_t)row * N_DIM + col] = o;
            }
        }
    }
}

// ---------------------------------------------------------------------------
extern "C" void kernel_launch(void* const* d_in, const int* in_sizes, int n_in,
                              void* d_out, int out_size)
{
    const float* x     = (const float*)d_in[0];
    const float* gamma = (const float*)d_in[1];
    const float* beta  = (const float*)d_in[2];
    const float* W     = (const float*)d_in[3];
    const float* b     = (const float*)d_in[4];
    float* out = (float*)d_out;

    ln_h_kernel<<<M_DIM / 4, 256>>>(x, gamma, beta);
    wt_h_kernel<<<dim3(N_DIM / 32, K_DIM / 64), dim3(32, 8)>>>(W);
    gemm_f16_kernel<<<dim3(N_DIM / BN, M_DIM / BM), 256>>>(b, out);
}